// round 16
// baseline (speedup 1.0000x reference)
#include <cuda_runtime.h>
#include <cuda_fp16.h>
#include <cstdint>

#define NSEQ 16384

__device__ __half g_Wh[4096 * 64];        // [ki][j] fp16 W
__device__ float  g_bias[4096];           // [ki]
__device__ __half g_xh[4 * 64 * NSEQ];    // fp16 copy of x, same layout

// smem byte offsets
#define SM_W     0                    // [128 n][64 j] fp16 swizzled (16384)
#define SM_BIAS  16384                // 128 f32                      (512)
#define SM_X     16896                // 3 bufs x 8192: [64 j][64 m] fp16 swizzled
#define SM_XBUF  8192
#define SM_EPI   (16896 + 3 * 8192)   // 8 warps x 2KB epilogue scratch (16384)
#define SM_TOTAL (SM_EPI + 16384)     // 57856

__device__ __forceinline__ uint32_t smem_u32(const void *p) {
    uint32_t a;
    asm("{ .reg .u64 t; cvta.to.shared.u64 t, %1; cvt.u32.u64 %0, t; }" : "=r"(a) : "l"(p));
    return a;
}
__device__ __forceinline__ uint32_t h2u(__half2 h) {
    return *reinterpret_cast<const uint32_t *>(&h);
}
__device__ __forceinline__ void ldsm4(uint32_t *r, uint32_t a) {
    asm volatile("ldmatrix.sync.aligned.m8n8.x4.shared.b16 {%0,%1,%2,%3}, [%4];"
                 : "=r"(r[0]), "=r"(r[1]), "=r"(r[2]), "=r"(r[3]) : "r"(a));
}
__device__ __forceinline__ void ldsm4t(uint32_t *r, uint32_t a) {
    asm volatile("ldmatrix.sync.aligned.m8n8.x4.trans.shared.b16 {%0,%1,%2,%3}, [%4];"
                 : "=r"(r[0]), "=r"(r[1]), "=r"(r[2]), "=r"(r[3]) : "r"(a));
}
__device__ __forceinline__ void mma16816(float *c, const uint32_t *a, uint32_t b0, uint32_t b1) {
    asm volatile("mma.sync.aligned.m16n8k16.row.col.f32.f16.f16.f32 "
                 "{%0,%1,%2,%3}, {%4,%5,%6,%7}, {%8,%9}, {%0,%1,%2,%3};"
                 : "+f"(c[0]), "+f"(c[1]), "+f"(c[2]), "+f"(c[3])
                 : "r"(a[0]), "r"(a[1]), "r"(a[2]), "r"(a[3]), "r"(b0), "r"(b1));
}
__device__ __forceinline__ void cpa16(uint32_t dst, const void *src) {
    asm volatile("cp.async.cg.shared.global [%0], [%1], 16;" :: "r"(dst), "l"(src));
}
__device__ __forceinline__ void cpa_commit() {
    asm volatile("cp.async.commit_group;" ::: "memory");
}
template <int N> __device__ __forceinline__ void cpa_wait() {
    asm volatile("cp.async.wait_group %0;" :: "n"(N) : "memory");
}
__device__ __forceinline__ void sts64(uint32_t a, float v0, float v1) {
    asm volatile("st.shared.v2.f32 [%0], {%1, %2};" :: "r"(a), "f"(v0), "f"(v1) : "memory");
}
__device__ __forceinline__ void lds128(float4 &v, uint32_t a) {
    asm volatile("ld.shared.v4.f32 {%0, %1, %2, %3}, [%4];"
                 : "=f"(v.x), "=f"(v.y), "=f"(v.z), "=f"(v.w) : "r"(a));
}

// ---------------------------------------------------------------------------
// Combined prep (one launch):
//   blocks [0, 1024):    x f32 -> fp16 g_xh (16 elems/thread)
//   blocks [1024, 1280): W -> fp16 g_Wh [ki][j] + bias[ki] = cm[k] . Wcm[k][i]
// ---------------------------------------------------------------------------
__global__ void prep_all(const float *__restrict__ x, const float *__restrict__ W,
                         const float *__restrict__ cm) {
    const int tid = threadIdx.x;
    if (blockIdx.x < 1024) {
        const int t = blockIdx.x * 256 + tid;
        const float4 *src = reinterpret_cast<const float4 *>(x) + (size_t)t * 4;
        uint4 *dst = reinterpret_cast<uint4 *>(g_xh) + (size_t)t * 2;
#pragma unroll
        for (int h = 0; h < 2; ++h) {
            float4 a = src[2 * h], b = src[2 * h + 1];
            uint32_t p0 = h2u(__float22half2_rn(make_float2(a.x, a.y)));
            uint32_t p1 = h2u(__float22half2_rn(make_float2(a.z, a.w)));
            uint32_t p2 = h2u(__float22half2_rn(make_float2(b.x, b.y)));
            uint32_t p3 = h2u(__float22half2_rn(make_float2(b.z, b.w)));
            dst[h] = make_uint4(p0, p1, p2, p3);
        }
    } else {
        const int pb = blockIdx.x - 1024;     // 0..255
#pragma unroll
        for (int t = 0; t < 4; ++t) {
            const int e = pb * 1024 + t * 256 + tid;   // (k, i, j) packed
            const int k = e >> 12, i = (e >> 6) & 63, j = e & 63;
            g_Wh[e] = __float2half_rn(W[(k * 64 + i) * 128 + j]);
        }
        if (tid < 16) {
            const int idx = pb * 16 + tid;    // ki
            const int k = idx >> 6, i = idx & 63;
            const float *cmk = cm + k * 64;
            const float *wc = W + (k * 64 + i) * 128 + 64;
            float s = 0.f;
#pragma unroll 8
            for (int j = 0; j < 64; ++j)
                s = fmaf(cmk[j], wc[j], s);
            g_bias[idx] = s;
        }
    }
}

// ---------------------------------------------------------------------------
// Main (R15 config + warp-local smem-transpose epilogue):
// 256 threads (8 warps = 4m x 2n), CTA tile 64m x 128ki, K=64, 16 m-tiles/CTA.
// Epilogue: normalized values STS.64 into per-warp 2KB scratch (swizzled),
// __syncwarp, LDS.128 + STG.128 with row-contiguous lanes -> 4 full-line
// wavefronts/instr instead of 8 fragmented ones (128 -> 16 wf per warp-h).
// ---------------------------------------------------------------------------
__global__ __launch_bounds__(256, 2)
void mma_kernel(float *__restrict__ out) {
    extern __shared__ char smem[];
    const uint32_t sb = smem_u32(smem);
    const int tid = threadIdx.x;
    const int lane = tid & 31, wid = tid >> 5;
    const int wm = wid & 3, wn = wid >> 2;
    const int ki0 = blockIdx.x * 128;
    const int grp = blockIdx.y;          // 0..63, 16 m-tiles of 64 each

    // ---- per-thread staging constants: 2 chunks (tid, tid+256) ----
    const int cj0 = tid >> 3, cp0 = tid & 7;
    const int cj1 = (tid + 256) >> 3, cp1 = tid & 7;
    const uint32_t d0 = sb + SM_X + (uint32_t)cj0 * 128 + (uint32_t)((cp0 ^ (cj0 & 7)) * 16);
    const uint32_t d1 = sb + SM_X + (uint32_t)cj1 * 128 + (uint32_t)((cp1 ^ (cj1 & 7)) * 16);

    auto stage_x = [&](int t, int buf) {
        const int m0 = (grp * 16 + t) * 64;
        const __half *xb = g_xh + ((size_t)(m0 >> 14) * 64) * NSEQ + (m0 & (NSEQ - 1));
        cpa16(d0 + (uint32_t)buf * SM_XBUF, xb + (size_t)cj0 * NSEQ + cp0 * 8);
        cpa16(d1 + (uint32_t)buf * SM_XBUF, xb + (size_t)cj1 * NSEQ + cp1 * 8);
        cpa_commit();
    };

    // prologue: start tiles 0,1
    stage_x(0, 0);
    stage_x(1, 1);

    // ---- stage W (swizzled, once) + bias ----
    {
#pragma unroll
        for (int q = 0; q < 4; ++q) {
            const int c = tid + q * 256;
            const int n = c >> 3, ch = c & 7;
            const uint4 w = *reinterpret_cast<const uint4 *>(g_Wh + (ki0 + n) * 64 + ch * 8);
            *reinterpret_cast<uint4 *>(smem + SM_W + n * 128 + ((ch ^ (n & 7)) * 16)) = w;
        }
        if (tid < 128) reinterpret_cast<float *>(smem + SM_BIAS)[tid] = g_bias[ki0 + tid];
    }

    cpa_wait<1>();        // tile 0 resident
    __syncthreads();

    // ---- hoist B (W tile) fragments: constant for whole CTA ----
    const int l7 = lane & 7;
    const int rBl = (lane & 7) + ((lane >> 4) << 3);
    const uint32_t aB0 = sb + SM_W + (uint32_t)(wn * 64 + rBl) * 128;
    const int selB = (lane >> 3) & 1;
    uint32_t B[4][4][4];
#pragma unroll
    for (int ks = 0; ks < 4; ++ks) {
        const uint32_t uB = (uint32_t)(((ks * 2 + selB) ^ l7) * 16);
#pragma unroll
        for (int p = 0; p < 4; ++p)
            ldsm4(B[ks][p], aB0 + p * 2048 + uB);
    }

    // A-frag (trans) lane constants
    const int jjl = (lane & 7) + ((lane >> 4) & 1) * 8;
    const int mcA = wm * 2 + ((lane >> 3) & 1);
    const uint32_t aA0 = sb + SM_X + (uint32_t)jjl * 128 + (uint32_t)((mcA ^ l7) * 16);

    const float *bsp = reinterpret_cast<const float *>(smem + SM_BIAS) + wn * 64 + (lane & 3) * 2;
    const float HI = 1.0f - 1e-5f;

    // epilogue scratch lane constants
    const uint32_t wepi = sb + SM_EPI + (uint32_t)wid * 2048;
    const int rl_st = lane >> 2;                       // write row (0..7)
    const uint32_t st_b = wepi + (uint32_t)rl_st * 256 + (uint32_t)((lane & 1) * 8);
    const int gq = (lane >> 1) & 1;                    // granule low bit at write
    const int rl_ld = lane >> 4;                       // read row offset (0..1)
    const int g_ld = lane & 15;                        // read granule

    int buf = 0;
#pragma unroll 1
    for (int t = 0; t < 16; ++t) {
        if (t + 2 < 16) {
            int b2i = buf + 2; if (b2i >= 3) b2i -= 3;
            stage_x(t + 2, b2i);
        }

        float acc[8][4];
#pragma unroll
        for (int nf = 0; nf < 8; ++nf)
#pragma unroll
            for (int c = 0; c < 4; ++c) acc[nf][c] = 0.f;

        const uint32_t aA = aA0 + (uint32_t)buf * SM_XBUF;
#pragma unroll
        for (int ks = 0; ks < 4; ++ks) {
            uint32_t Af[4];
            ldsm4t(Af, aA + (uint32_t)ks * 2048);
#pragma unroll
            for (int p = 0; p < 4; ++p) {
                mma16816(acc[2 * p],     Af, B[ks][p][0], B[ks][p][1]);
                mma16816(acc[2 * p + 1], Af, B[ks][p][2], B[ks][p][3]);
            }
        }

        // ---- epilogue: bias + clip + L1-normalize + smem-transposed STG.128 ----
        const int m0 = (grp * 16 + t) * 64;
#pragma unroll
        for (int h = 0; h < 2; ++h) {
            float v[8][2];
            float s = 0.f;
#pragma unroll
            for (int nf = 0; nf < 8; ++nf) {
                const float2 bb = *reinterpret_cast<const float2 *>(bsp + nf * 8);
                const float v0 = fminf(fmaxf(acc[nf][2 * h]     + bb.x, 1e-5f), HI);
                const float v1 = fminf(fmaxf(acc[nf][2 * h + 1] + bb.y, 1e-5f), HI);
                v[nf][0] = v0; v[nf][1] = v1;
                s += v0 + v1;
            }
            s += __shfl_xor_sync(0xffffffffu, s, 1);
            s += __shfl_xor_sync(0xffffffffu, s, 2);
            const float inv = __fdividef(1.0f, s);

            // write normalized values into warp scratch (swizzle g ^ (row<<1))
#pragma unroll
            for (int nf = 0; nf < 8; ++nf) {
                const int g = nf * 2 + gq;
                sts64(st_b + (uint32_t)(((g ^ (rl_st << 1)) & 15) * 16),
                      v[nf][0] * inv, v[nf][1] * inv);
            }
            __syncwarp();

            // read back row-contiguous and store: instr k = rows 2k, 2k+1 full
            float *orow = out + (size_t)(m0 + wm * 16 + h * 8) * 4096 + ki0 + wn * 64;
#pragma unroll
            for (int k = 0; k < 4; ++k) {
                const int r = 2 * k + rl_ld;
                float4 vv;
                lds128(vv, wepi + (uint32_t)(r * 256 + ((g_ld ^ (r << 1)) & 15) * 16));
                *reinterpret_cast<float4 *>(orow + (size_t)r * 4096 + g_ld * 4) = vv;
            }
            __syncwarp();   // scratch reusable for next h / tile
        }

        if (t + 2 < 16) cpa_wait<1>();   // tile t+1 resident (t+2 may be in flight)
        else            cpa_wait<0>();
        if (t < 15) __syncthreads();

        if (++buf == 3) buf = 0;
    }
}

// ---------------------------------------------------------------------------
extern "C" void kernel_launch(void *const *d_in, const int *in_sizes, int n_in,
                              void *d_out, int out_size) {
    const float *x  = (const float *)d_in[0];   // (4, 64, 16384) f32
    const float *cm = (const float *)d_in[1];   // (64, 64) f32
    const float *W  = (const float *)d_in[2];   // (64, 64, 128) f32
    float *out = (float *)d_out;                // (65536, 4096) f32

    (void)in_sizes; (void)n_in; (void)out_size;

    cudaFuncSetAttribute(mma_kernel, cudaFuncAttributeMaxDynamicSharedMemorySize, SM_TOTAL);
    prep_all<<<1280, 256>>>(x, W, cm);
    mma_kernel<<<dim3(32, 64), 256, SM_TOTAL>>>(out);
}

// round 17
// speedup vs baseline: 1.5293x; 1.5293x over previous
#include <cuda_runtime.h>
#include <cuda_fp16.h>
#include <cstdint>

#define NSEQ 16384

__device__ __half g_Wh[4096 * 64];        // [ki][j] fp16 W
__device__ float  g_bias[4096];           // [ki]
__device__ __half g_xh[4 * 64 * NSEQ];    // fp16 copy of x, same layout

// smem byte offsets
#define SM_W     0                    // [128 n][64 j] fp16 swizzled (16384)
#define SM_BIAS  16384                // 128 f32                      (512)
#define SM_X     16896                // 3 bufs x 8192: [64 j][64 m] fp16 swizzled
#define SM_XBUF  8192
#define SM_TOTAL (16896 + 3 * 8192)   // 41472

__device__ __forceinline__ uint32_t smem_u32(const void *p) {
    uint32_t a;
    asm("{ .reg .u64 t; cvta.to.shared.u64 t, %1; cvt.u32.u64 %0, t; }" : "=r"(a) : "l"(p));
    return a;
}
__device__ __forceinline__ uint32_t h2u(__half2 h) {
    return *reinterpret_cast<const uint32_t *>(&h);
}
__device__ __forceinline__ void ldsm4(uint32_t *r, uint32_t a) {
    asm volatile("ldmatrix.sync.aligned.m8n8.x4.shared.b16 {%0,%1,%2,%3}, [%4];"
                 : "=r"(r[0]), "=r"(r[1]), "=r"(r[2]), "=r"(r[3]) : "r"(a));
}
__device__ __forceinline__ void ldsm4t(uint32_t *r, uint32_t a) {
    asm volatile("ldmatrix.sync.aligned.m8n8.x4.trans.shared.b16 {%0,%1,%2,%3}, [%4];"
                 : "=r"(r[0]), "=r"(r[1]), "=r"(r[2]), "=r"(r[3]) : "r"(a));
}
__device__ __forceinline__ void mma16816(float *c, const uint32_t *a, uint32_t b0, uint32_t b1) {
    asm volatile("mma.sync.aligned.m16n8k16.row.col.f32.f16.f16.f32 "
                 "{%0,%1,%2,%3}, {%4,%5,%6,%7}, {%8,%9}, {%0,%1,%2,%3};"
                 : "+f"(c[0]), "+f"(c[1]), "+f"(c[2]), "+f"(c[3])
                 : "r"(a[0]), "r"(a[1]), "r"(a[2]), "r"(a[3]), "r"(b0), "r"(b1));
}
__device__ __forceinline__ void cpa16(uint32_t dst, const void *src) {
    asm volatile("cp.async.cg.shared.global [%0], [%1], 16;" :: "r"(dst), "l"(src));
}
__device__ __forceinline__ void cpa_commit() {
    asm volatile("cp.async.commit_group;" ::: "memory");
}
template <int N> __device__ __forceinline__ void cpa_wait() {
    asm volatile("cp.async.wait_group %0;" :: "n"(N) : "memory");
}

// ---------------------------------------------------------------------------
// Combined prep (one launch):
//   blocks [0, 1024):    x f32 -> fp16 g_xh (16 elems/thread)
//   blocks [1024, 1280): W -> fp16 g_Wh [ki][j] + bias[ki] = cm[k] . Wcm[k][i]
// ---------------------------------------------------------------------------
__global__ void prep_all(const float *__restrict__ x, const float *__restrict__ W,
                         const float *__restrict__ cm) {
    const int tid = threadIdx.x;
    if (blockIdx.x < 1024) {
        const int t = blockIdx.x * 256 + tid;
        const float4 *src = reinterpret_cast<const float4 *>(x) + (size_t)t * 4;
        uint4 *dst = reinterpret_cast<uint4 *>(g_xh) + (size_t)t * 2;
#pragma unroll
        for (int h = 0; h < 2; ++h) {
            float4 a = src[2 * h], b = src[2 * h + 1];
            uint32_t p0 = h2u(__float22half2_rn(make_float2(a.x, a.y)));
            uint32_t p1 = h2u(__float22half2_rn(make_float2(a.z, a.w)));
            uint32_t p2 = h2u(__float22half2_rn(make_float2(b.x, b.y)));
            uint32_t p3 = h2u(__float22half2_rn(make_float2(b.z, b.w)));
            dst[h] = make_uint4(p0, p1, p2, p3);
        }
    } else {
        const int pb = blockIdx.x - 1024;     // 0..255
#pragma unroll
        for (int t = 0; t < 4; ++t) {
            const int e = pb * 1024 + t * 256 + tid;   // (k, i, j) packed
            const int k = e >> 12, i = (e >> 6) & 63, j = e & 63;
            g_Wh[e] = __float2half_rn(W[(k * 64 + i) * 128 + j]);
        }
        if (tid < 16) {
            const int idx = pb * 16 + tid;    // ki
            const int k = idx >> 6, i = idx & 63;
            const float *cmk = cm + k * 64;
            const float *wc = W + (k * 64 + i) * 128 + 64;
            float s = 0.f;
#pragma unroll 8
            for (int j = 0; j < 64; ++j)
                s = fmaf(cmk[j], wc[j], s);
            g_bias[idx] = s;
        }
    }
}

// ---------------------------------------------------------------------------
// Main (final form -- empirically fastest across 10 structural variants):
// 256 threads (8 warps = 4m x 2n), CTA tile 64m x 128ki, K=64, 16 m-tiles/CTA.
// X staged via cp.async (3 buffers, 2 ahead), A frags via ldmatrix.trans,
// B hoisted to regs once, bias read from smem in epilogue, fresh per-tile
// addressing, plain coalesced float2 stores. 2 CTAs/SM.
// ---------------------------------------------------------------------------
__global__ __launch_bounds__(256, 2)
void mma_kernel(float *__restrict__ out) {
    extern __shared__ char smem[];
    const uint32_t sb = smem_u32(smem);
    const int tid = threadIdx.x;
    const int lane = tid & 31, wid = tid >> 5;
    const int wm = wid & 3, wn = wid >> 2;
    const int ki0 = blockIdx.x * 128;
    const int grp = blockIdx.y;          // 0..63, 16 m-tiles of 64 each

    // ---- per-thread staging constants: 2 chunks (tid, tid+256) ----
    const int cj0 = tid >> 3, cp0 = tid & 7;
    const int cj1 = (tid + 256) >> 3, cp1 = tid & 7;
    const uint32_t d0 = sb + SM_X + (uint32_t)cj0 * 128 + (uint32_t)((cp0 ^ (cj0 & 7)) * 16);
    const uint32_t d1 = sb + SM_X + (uint32_t)cj1 * 128 + (uint32_t)((cp1 ^ (cj1 & 7)) * 16);

    auto stage_x = [&](int t, int buf) {
        const int m0 = (grp * 16 + t) * 64;
        const __half *xb = g_xh + ((size_t)(m0 >> 14) * 64) * NSEQ + (m0 & (NSEQ - 1));
        cpa16(d0 + (uint32_t)buf * SM_XBUF, xb + (size_t)cj0 * NSEQ + cp0 * 8);
        cpa16(d1 + (uint32_t)buf * SM_XBUF, xb + (size_t)cj1 * NSEQ + cp1 * 8);
        cpa_commit();
    };

    // prologue: start tiles 0,1
    stage_x(0, 0);
    stage_x(1, 1);

    // ---- stage W (swizzled, once) + bias ----
    {
#pragma unroll
        for (int q = 0; q < 4; ++q) {
            const int c = tid + q * 256;
            const int n = c >> 3, ch = c & 7;
            const uint4 w = *reinterpret_cast<const uint4 *>(g_Wh + (ki0 + n) * 64 + ch * 8);
            *reinterpret_cast<uint4 *>(smem + SM_W + n * 128 + ((ch ^ (n & 7)) * 16)) = w;
        }
        if (tid < 128) reinterpret_cast<float *>(smem + SM_BIAS)[tid] = g_bias[ki0 + tid];
    }

    cpa_wait<1>();        // tile 0 resident
    __syncthreads();

    // ---- hoist B (W tile) fragments: constant for whole CTA ----
    const int l7 = lane & 7;
    const int rBl = (lane & 7) + ((lane >> 4) << 3);
    const uint32_t aB0 = sb + SM_W + (uint32_t)(wn * 64 + rBl) * 128;
    const int selB = (lane >> 3) & 1;
    uint32_t B[4][4][4];
#pragma unroll
    for (int ks = 0; ks < 4; ++ks) {
        const uint32_t uB = (uint32_t)(((ks * 2 + selB) ^ l7) * 16);
#pragma unroll
        for (int p = 0; p < 4; ++p)
            ldsm4(B[ks][p], aB0 + p * 2048 + uB);
    }

    // A-frag (trans) lane constants
    const int jjl = (lane & 7) + ((lane >> 4) & 1) * 8;
    const int mcA = wm * 2 + ((lane >> 3) & 1);
    const uint32_t aA0 = sb + SM_X + (uint32_t)jjl * 128 + (uint32_t)((mcA ^ l7) * 16);

    const float *bsp = reinterpret_cast<const float *>(smem + SM_BIAS) + wn * 64 + (lane & 3) * 2;
    const float HI = 1.0f - 1e-5f;

    int buf = 0;
#pragma unroll 1
    for (int t = 0; t < 16; ++t) {
        if (t + 2 < 16) {
            int b2i = buf + 2; if (b2i >= 3) b2i -= 3;
            stage_x(t + 2, b2i);
        }

        float acc[8][4];
#pragma unroll
        for (int nf = 0; nf < 8; ++nf)
#pragma unroll
            for (int c = 0; c < 4; ++c) acc[nf][c] = 0.f;

        const uint32_t aA = aA0 + (uint32_t)buf * SM_XBUF;
#pragma unroll
        for (int ks = 0; ks < 4; ++ks) {
            uint32_t Af[4];
            ldsm4t(Af, aA + (uint32_t)ks * 2048);
#pragma unroll
            for (int p = 0; p < 4; ++p) {
                mma16816(acc[2 * p],     Af, B[ks][p][0], B[ks][p][1]);
                mma16816(acc[2 * p + 1], Af, B[ks][p][2], B[ks][p][3]);
            }
        }

        // ---- epilogue: bias + clip + L1-normalize + direct store ----
        const int m0 = (grp * 16 + t) * 64;
#pragma unroll
        for (int h = 0; h < 2; ++h) {
            float v[8][2];
            float s = 0.f;
#pragma unroll
            for (int nf = 0; nf < 8; ++nf) {
                const float2 bb = *reinterpret_cast<const float2 *>(bsp + nf * 8);
                const float v0 = fminf(fmaxf(acc[nf][2 * h]     + bb.x, 1e-5f), HI);
                const float v1 = fminf(fmaxf(acc[nf][2 * h + 1] + bb.y, 1e-5f), HI);
                v[nf][0] = v0; v[nf][1] = v1;
                s += v0 + v1;
            }
            s += __shfl_xor_sync(0xffffffffu, s, 1);
            s += __shfl_xor_sync(0xffffffffu, s, 2);
            const float inv = __fdividef(1.0f, s);
            const int row = wm * 16 + (lane >> 2) + h * 8;
            float *op = out + (size_t)(m0 + row) * 4096 + ki0 + wn * 64 + (lane & 3) * 2;
#pragma unroll
            for (int nf = 0; nf < 8; ++nf)
                *reinterpret_cast<float2 *>(op + nf * 8) =
                    make_float2(v[nf][0] * inv, v[nf][1] * inv);
        }

        if (t + 2 < 16) cpa_wait<1>();   // tile t+1 resident (t+2 may be in flight)
        else            cpa_wait<0>();
        if (t < 15) __syncthreads();

        if (++buf == 3) buf = 0;
    }
}

// ---------------------------------------------------------------------------
extern "C" void kernel_launch(void *const *d_in, const int *in_sizes, int n_in,
                              void *d_out, int out_size) {
    const float *x  = (const float *)d_in[0];   // (4, 64, 16384) f32
    const float *cm = (const float *)d_in[1];   // (64, 64) f32
    const float *W  = (const float *)d_in[2];   // (64, 64, 128) f32
    float *out = (float *)d_out;                // (65536, 4096) f32

    (void)in_sizes; (void)n_in; (void)out_size;

    cudaFuncSetAttribute(mma_kernel, cudaFuncAttributeMaxDynamicSharedMemorySize, SM_TOTAL);
    prep_all<<<1280, 256>>>(x, W, cm);
    mma_kernel<<<dim3(32, 64), 256, SM_TOTAL>>>(out);
}